// round 4
// baseline (speedup 1.0000x reference)
#include <cuda_runtime.h>
#include <math.h>

#define BB 2
#define NN 2048
#define DM 512
#define NH 8
#define HD 64
#define TOPK 64
#define BH (BB*NH)       // 16
#define M_TOT (BB*NN)    // 4096
#define SCALEF 0.125f

// ---------------- scratch (static __device__ per allocation rules) ----------
__device__ float g_Qh[BH*NN*HD];            // [bh][n][d]  (Q pre-scaled by 1/8)
__device__ float g_Kh[BH*NN*HD];
__device__ float g_Vh[BH*NN*HD];
__device__ float g_S[(size_t)BH*NN*NN];     // raw scores 256MB
__device__ float g_H[M_TOT*DM];             // merged-head attn output

// ---------------------------------------------------------------------------
// 128x128-tile fp32 GEMM, 8x8 micro-tile, BK=16, 256 threads, double-buffered.
// mode 0: fused QKV (head-split out, Q scaled). mode 1: out-proj from g_H.
// ---------------------------------------------------------------------------
__global__ __launch_bounds__(256)
void gemm128(const float* __restrict__ X0, const float* __restrict__ X1,
             const float* __restrict__ X2,
             const float* __restrict__ W0, const float* __restrict__ W1,
             const float* __restrict__ W2,
             const float* __restrict__ b0, const float* __restrict__ b1,
             const float* __restrict__ b2,
             float* __restrict__ outp, int mode)
{
    __shared__ float XsT[2][16][132];
    __shared__ float WsT[2][16][132];

    const int tid = threadIdx.x;
    const int tx = tid & 15, ty = tid >> 4;
    const int m0 = blockIdx.y * 128;

    int which = 0, o0 = 0;
    const float *X, *W, *bias;
    if (mode == 0) {
        which = blockIdx.x >> 2;
        o0 = (blockIdx.x & 3) * 128;
        X    = (which == 0) ? X0 : (which == 1) ? X1 : X2;
        W    = (which == 0) ? W0 : (which == 1) ? W1 : W2;
        bias = (which == 0) ? b0 : (which == 1) ? b1 : b2;
    } else {
        o0 = blockIdx.x * 128;
        X = g_H; W = W0; bias = b0;
    }

    const int lr  = tid >> 2;
    const int lc4 = (tid & 3) * 4;

    float acc[8][8];
#pragma unroll
    for (int i = 0; i < 8; i++)
#pragma unroll
        for (int j = 0; j < 8; j++) acc[i][j] = 0.f;

    float4 xr[2], wr[2];
#pragma unroll
    for (int j = 0; j < 2; j++) {
        int r = lr + j * 64;
        xr[j] = *(const float4*)&X[(size_t)(m0 + r) * DM + lc4];
        wr[j] = *(const float4*)&W[(size_t)(o0 + r) * DM + lc4];
    }
#pragma unroll
    for (int j = 0; j < 2; j++) {
        int r = lr + j * 64;
        XsT[0][lc4 + 0][r] = xr[j].x; XsT[0][lc4 + 1][r] = xr[j].y;
        XsT[0][lc4 + 2][r] = xr[j].z; XsT[0][lc4 + 3][r] = xr[j].w;
        WsT[0][lc4 + 0][r] = wr[j].x; WsT[0][lc4 + 1][r] = wr[j].y;
        WsT[0][lc4 + 2][r] = wr[j].z; WsT[0][lc4 + 3][r] = wr[j].w;
    }
    __syncthreads();

    int p = 0;
    for (int k0 = 0; k0 < DM; k0 += 16) {
        const int kn = k0 + 16;
        if (kn < DM) {
#pragma unroll
            for (int j = 0; j < 2; j++) {
                int r = lr + j * 64;
                xr[j] = *(const float4*)&X[(size_t)(m0 + r) * DM + kn + lc4];
                wr[j] = *(const float4*)&W[(size_t)(o0 + r) * DM + kn + lc4];
            }
        }
#pragma unroll
        for (int kk = 0; kk < 16; kk++) {
            float4 a0 = *(const float4*)&XsT[p][kk][ty * 4];
            float4 a1 = *(const float4*)&XsT[p][kk][64 + ty * 4];
            float4 bv0 = *(const float4*)&WsT[p][kk][tx * 4];
            float4 bv1 = *(const float4*)&WsT[p][kk][64 + tx * 4];
            float a[8] = {a0.x, a0.y, a0.z, a0.w, a1.x, a1.y, a1.z, a1.w};
            float b[8] = {bv0.x, bv0.y, bv0.z, bv0.w, bv1.x, bv1.y, bv1.z, bv1.w};
#pragma unroll
            for (int i = 0; i < 8; i++)
#pragma unroll
                for (int j = 0; j < 8; j++) acc[i][j] += a[i] * b[j];
        }
        if (kn < DM) {
            int pn = p ^ 1;
#pragma unroll
            for (int j = 0; j < 2; j++) {
                int r = lr + j * 64;
                XsT[pn][lc4 + 0][r] = xr[j].x; XsT[pn][lc4 + 1][r] = xr[j].y;
                XsT[pn][lc4 + 2][r] = xr[j].z; XsT[pn][lc4 + 3][r] = xr[j].w;
                WsT[pn][lc4 + 0][r] = wr[j].x; WsT[pn][lc4 + 1][r] = wr[j].y;
                WsT[pn][lc4 + 2][r] = wr[j].z; WsT[pn][lc4 + 3][r] = wr[j].w;
            }
        }
        __syncthreads();
        p ^= 1;
    }

    const float sc = (mode == 0 && which == 0) ? SCALEF : 1.f;
#pragma unroll
    for (int i = 0; i < 8; i++) {
        int m = m0 + ((i < 4) ? ty * 4 + i : 64 + ty * 4 + (i - 4));
#pragma unroll
        for (int jg = 0; jg < 2; jg++) {
            int oc = o0 + ((jg == 0) ? tx * 4 : 64 + tx * 4);
            float4 v;
            v.x = (acc[i][jg * 4 + 0] + bias[oc + 0]) * sc;
            v.y = (acc[i][jg * 4 + 1] + bias[oc + 1]) * sc;
            v.z = (acc[i][jg * 4 + 2] + bias[oc + 2]) * sc;
            v.w = (acc[i][jg * 4 + 3] + bias[oc + 3]) * sc;
            if (mode == 0) {
                int b = m >> 11, n = m & (NN - 1);
                int h = oc >> 6, d = oc & 63;
                float* dst = (which == 0) ? g_Qh : (which == 1) ? g_Kh : g_Vh;
                *(float4*)&dst[(size_t)((b * NH + h) * NN + n) * HD + d] = v;
            } else {
                *(float4*)&outp[(size_t)m * DM + oc] = v;
            }
        }
    }
}

// ---------------------------------------------------------------------------
// Scores: per (b,h), S = Qh(2048x64) @ Kh^T (Q pre-scaled). 128x128 tiles,
// full K-dim (=64) resident, one sync. grid (16,16,16), 256 threads.
// ---------------------------------------------------------------------------
__global__ __launch_bounds__(256)
void scores_kernel()
{
    extern __shared__ float smem_sc[];
    float (*QsT)[132] = (float(*)[132])smem_sc;              // [64][132]
    float (*KsT)[132] = (float(*)[132])(smem_sc + 64 * 132);

    const int bh = blockIdx.z;
    const int kx = blockIdx.x * 128;
    const int qy = blockIdx.y * 128;
    const int tid = threadIdx.x;
    const int tx = tid & 15, ty = tid >> 4;

#pragma unroll
    for (int j = 0; j < 8; j++) {
        int i = tid + j * 256;
        int r = i >> 4, c4 = (i & 15) * 4;
        float4 qv = *(const float4*)&g_Qh[((size_t)bh * NN + qy + r) * HD + c4];
        QsT[c4 + 0][r] = qv.x; QsT[c4 + 1][r] = qv.y;
        QsT[c4 + 2][r] = qv.z; QsT[c4 + 3][r] = qv.w;
        float4 kv = *(const float4*)&g_Kh[((size_t)bh * NN + kx + r) * HD + c4];
        KsT[c4 + 0][r] = kv.x; KsT[c4 + 1][r] = kv.y;
        KsT[c4 + 2][r] = kv.z; KsT[c4 + 3][r] = kv.w;
    }
    __syncthreads();

    float acc[8][8];
#pragma unroll
    for (int i = 0; i < 8; i++)
#pragma unroll
        for (int j = 0; j < 8; j++) acc[i][j] = 0.f;

#pragma unroll 8
    for (int d = 0; d < 64; d++) {
        float4 a0 = *(const float4*)&QsT[d][ty * 4];
        float4 a1 = *(const float4*)&QsT[d][64 + ty * 4];
        float4 bv0 = *(const float4*)&KsT[d][tx * 4];
        float4 bv1 = *(const float4*)&KsT[d][64 + tx * 4];
        float a[8] = {a0.x, a0.y, a0.z, a0.w, a1.x, a1.y, a1.z, a1.w};
        float b[8] = {bv0.x, bv0.y, bv0.z, bv0.w, bv1.x, bv1.y, bv1.z, bv1.w};
#pragma unroll
        for (int i = 0; i < 8; i++)
#pragma unroll
            for (int j = 0; j < 8; j++) acc[i][j] += a[i] * b[j];
    }

#pragma unroll
    for (int i = 0; i < 8; i++) {
        int row = qy + ((i < 4) ? ty * 4 + i : 64 + ty * 4 + (i - 4));
#pragma unroll
        for (int jg = 0; jg < 2; jg++) {
            int col = kx + ((jg == 0) ? tx * 4 : 64 + tx * 4);
            float4 v = make_float4(acc[i][jg * 4 + 0], acc[i][jg * 4 + 1],
                                   acc[i][jg * 4 + 2], acc[i][jg * 4 + 3]);
            __stcs((float4*)&g_S[((size_t)bh * NN + row) * NN + col], v);
        }
    }
}

// ---------------------------------------------------------------------------
// Per-row topk + softmax + AV.  NEW: single 2048-bin (11-bit) histogram +
// in-bin exact refinement, ~13 syncs total (was ~24 + 3 extra radix rounds).
// grid 32768 x 256; thread t owns columns t*8..t*8+7.
// ---------------------------------------------------------------------------
__global__ __launch_bounds__(256)
void topk_av(float* __restrict__ attn, int write_attn)
{
    const int row = blockIdx.x;           // bh*N + q
    const int bh  = row >> 11;
    const int q   = row & (NN - 1);
    const int tid = threadIdx.x;
    const int lane = tid & 31, wid = tid >> 5;

    __shared__ int hist[2048];
    __shared__ unsigned cand[512];
    __shared__ int wsum[8], wsuf[8];
    __shared__ float redf[8];
    __shared__ int   sidx[128];
    __shared__ float sw[128];
    __shared__ float pacc[256];
    __shared__ int sh_bin, sh_bin2, sh_m, sh_c, sh_cnt;
    __shared__ unsigned sh_kth;
    __shared__ float sh_rmax, sh_invz;

    // ---- load 8 scores (two float4), build monotone uint keys ----
    const float4* Srow = (const float4*)&g_S[(size_t)row * NN];
    float4 v0 = __ldcs(&Srow[tid * 2]);
    float4 v1 = __ldcs(&Srow[tid * 2 + 1]);
    float sreg[8] = {v0.x, v0.y, v0.z, v0.w, v1.x, v1.y, v1.z, v1.w};
    unsigned keys[8];
#pragma unroll
    for (int e = 0; e < 8; e++) {
        unsigned u = __float_as_uint(sreg[e]);
        keys[e] = (u & 0x80000000u) ? ~u : (u | 0x80000000u);
    }

    // ---- phase 1: 2048-bin histogram of top-11 key bits ----
#pragma unroll
    for (int j = 0; j < 8; j++) hist[tid + j * 256] = 0;
    if (tid == 0) { sh_c = 0; sh_cnt = 0; sh_bin2 = -1; sh_kth = 0u; }
    __syncthreads();                                          // S1
#pragma unroll
    for (int e = 0; e < 8; e++) {
        unsigned bin = keys[e] >> 21;
        unsigned mm = __match_any_sync(0xffffffffu, bin);
        if ((int)(__ffs(mm) - 1) == lane) atomicAdd(&hist[bin], __popc(mm));
    }
    __syncthreads();                                          // S2

    // ---- phase 2: hierarchical suffix-scan -> threshold bin B, rank m ----
    {
        int4 h0 = *(const int4*)&hist[tid * 8];
        int4 h1 = *(const int4*)&hist[tid * 8 + 4];
        int lh[8] = {h0.x, h0.y, h0.z, h0.w, h1.x, h1.y, h1.z, h1.w};
        int ls[8];
        int suf = 0;
#pragma unroll
        for (int i = 7; i >= 0; i--) { suf += lh[i]; ls[i] = suf; }
        const int T = suf;
        int s = T;                         // inclusive suffix within warp
#pragma unroll
        for (int off = 1; off < 32; off <<= 1) {
            int t = __shfl_down_sync(0xffffffffu, s, off);
            if (lane + off < 32) s += t;
        }
        if (lane == 0) wsum[wid] = s;
        __syncthreads();                                      // S3
        if (tid < 8) {
            int t = 0;
            for (int j = tid + 1; j < 8; j++) t += wsum[j];
            wsuf[tid] = t;
        }
        __syncthreads();                                      // S4
        const int G = (s - T) + wsuf[wid]; // count in bins strictly above group
#pragma unroll
        for (int i = 0; i < 8; i++) {
            int ge = ls[i] + G;
            int gt = ge - lh[i];
            if (ge >= TOPK && gt < TOPK && lh[i] > 0) {
                sh_bin = tid * 8 + i;
                sh_m = TOPK - gt;          // need m-th largest within bin
            }
        }
    }
    __syncthreads();                                          // S5
    const int B = sh_bin;

    // ---- optional refinement if threshold bin overly populated ----
    if (hist[B] > 512) {
        hist[tid] = 0;
        __syncthreads();
#pragma unroll
        for (int e = 0; e < 8; e++)
            if ((keys[e] >> 21) == (unsigned)B)
                atomicAdd(&hist[(keys[e] >> 13) & 255u], 1);
        __syncthreads();
        int v = hist[tid];
        int s = v;
#pragma unroll
        for (int off = 1; off < 32; off <<= 1) {
            int t = __shfl_down_sync(0xffffffffu, s, off);
            if (lane + off < 32) s += t;
        }
        if (lane == 0) wsum[wid] = s;
        __syncthreads();
        if (tid < 8) {
            int t = 0;
            for (int j = tid + 1; j < 8; j++) t += wsum[j];
            wsuf[tid] = t;
        }
        __syncthreads();
        int m_loc = sh_m;
        int S2 = s + wsuf[wid];
        if (S2 >= m_loc && S2 - v < m_loc && v > 0) {
            sh_bin2 = tid;
            sh_m = m_loc - (S2 - v);
        }
        __syncthreads();
    }
    const int B2 = sh_bin2;

    // ---- collect candidates ----
#pragma unroll
    for (int e = 0; e < 8; e++) {
        bool match = (B2 < 0) ? ((keys[e] >> 21) == (unsigned)B)
                              : ((keys[e] >> 13) == (((unsigned)B << 8) | (unsigned)B2));
        if (match) {
            int p = atomicAdd(&sh_c, 1);
            if (p < 512) cand[p] = keys[e];
        }
    }
    __syncthreads();                                          // S6
    const int c = (sh_c < 512) ? sh_c : 512;
    const int m = sh_m;

    // ---- exact m-th largest among c candidates (broadcast reads) ----
#pragma unroll
    for (int rep = 0; rep < 2; rep++) {
        int j = tid + rep * 256;
        if (j < c) {
            unsigned mykey = cand[j];
            int gt = 0, eq = 0;
            for (int i = 0; i < c; i++) {
                unsigned x = cand[i];
                gt += (x > mykey);
                eq += (x == mykey);
            }
            if (gt < m && gt + eq >= m) sh_kth = mykey;
        }
    }
    __syncthreads();                                          // S7
    const unsigned kth = sh_kth;

    // ---- row max ----
    float lmax = -3.4e38f;
#pragma unroll
    for (int e = 0; e < 8; e++) lmax = fmaxf(lmax, sreg[e]);
#pragma unroll
    for (int off = 16; off > 0; off >>= 1)
        lmax = fmaxf(lmax, __shfl_xor_sync(0xffffffffu, lmax, off));
    if (lane == 0) redf[wid] = lmax;
    __syncthreads();                                          // S8
    if (tid == 0) {
        float mx = redf[0];
        for (int j = 1; j < 8; j++) mx = fmaxf(mx, redf[j]);
        sh_rmax = mx;
    }
    __syncthreads();                                          // S9
    const float rmax = sh_rmax;

    // ---- exp (once) + sum over selected ----
    float ex[8];
    float lsum = 0.f;
#pragma unroll
    for (int e = 0; e < 8; e++) {
        bool sel = (keys[e] >= kth);
        ex[e] = sel ? __expf(sreg[e] - rmax) : 0.f;
        lsum += ex[e];
    }
#pragma unroll
    for (int off = 16; off > 0; off >>= 1)
        lsum += __shfl_xor_sync(0xffffffffu, lsum, off);
    if (lane == 0) redf[wid] = lsum;
    __syncthreads();                                          // S10
    if (tid == 0) {
        float z = 0.f;
        for (int j = 0; j < 8; j++) z += redf[j];
        sh_invz = 1.f / z;
    }
    __syncthreads();                                          // S11
    const float inv_z = sh_invz;

    // ---- weights: write attn row, gather selected ----
    float w[8];
#pragma unroll
    for (int e = 0; e < 8; e++) {
        w[e] = ex[e] * inv_z;
        if (keys[e] >= kth) {
            int p = atomicAdd(&sh_cnt, 1);
            if (p < 128) { sidx[p] = tid * 8 + e; sw[p] = w[e]; }
        }
    }
    if (write_attn) {
        float4* Arow = (float4*)&attn[(size_t)row * NN];
        __stcs(&Arow[tid * 2],     make_float4(w[0], w[1], w[2], w[3]));
        __stcs(&Arow[tid * 2 + 1], make_float4(w[4], w[5], w[6], w[7]));
    }
    __syncthreads();                                          // S12
    int cnt = sh_cnt; if (cnt > 128) cnt = 128;

    // ---- AV: out[d] = sum_j w_j * V[bh][idx_j][d] ----
    const int d = tid & 63;
    const int part = tid >> 6;
    float acc = 0.f;
    for (int j = part; j < cnt; j += 4)
        acc += sw[j] * g_Vh[(size_t)(bh * NN + sidx[j]) * HD + d];
    pacc[tid] = acc;
    __syncthreads();                                          // S13
    if (tid < 64) {
        float o = pacc[tid] + pacc[64 + tid] + pacc[128 + tid] + pacc[192 + tid];
        int b = bh >> 3, h = bh & 7;
        g_H[(size_t)(b * NN + q) * DM + h * HD + tid] = o;
    }
}

// ---------------------------------------------------------------------------
extern "C" void kernel_launch(void* const* d_in, const int* in_sizes, int n_in,
                              void* d_out, int out_size)
{
    const float* q  = (const float*)d_in[0];
    const float* k  = (const float*)d_in[1];
    const float* v  = (const float*)d_in[2];
    const float* wq = (const float*)d_in[3];
    const float* bq = (const float*)d_in[4];
    const float* wk = (const float*)d_in[5];
    const float* bk = (const float*)d_in[6];
    const float* wv = (const float*)d_in[7];
    const float* bv = (const float*)d_in[8];
    const float* wo = (const float*)d_in[9];
    const float* bo = (const float*)d_in[10];

    float* out = (float*)d_out;
    const long long OUT_ELEMS  = (long long)M_TOT * DM;        // 2,097,152
    const long long ATTN_ELEMS = (long long)BH * NN * NN;      // 67,108,864

    int write_attn = 0, write_out = 1;
    float* attn_ptr = nullptr;
    if ((long long)out_size >= OUT_ELEMS + ATTN_ELEMS) {
        write_attn = 1; attn_ptr = out + OUT_ELEMS;
    } else if ((long long)out_size == ATTN_ELEMS) {
        write_attn = 1; attn_ptr = out; write_out = 0;
    }

    const int SC_SMEM = 2 * 64 * 132 * 4;   // 67584 bytes
    cudaFuncSetAttribute(scores_kernel,
                         cudaFuncAttributeMaxDynamicSharedMemorySize, SC_SMEM);

    gemm128<<<dim3(12, M_TOT / 128), 256>>>(q, k, v, wq, wk, wv, bq, bk, bv,
                                            nullptr, 0);

    scores_kernel<<<dim3(NN / 128, NN / 128, BH), 256, SC_SMEM>>>();

    topk_av<<<BH * NN, 256>>>(attn_ptr, write_attn);

    if (write_out)
        gemm128<<<dim3(DM / 128, M_TOT / 128), 256>>>(nullptr, nullptr, nullptr,
                                                      wo, nullptr, nullptr,
                                                      bo, nullptr, nullptr,
                                                      out, 1);
}

// round 5
// speedup vs baseline: 1.1204x; 1.1204x over previous
#include <cuda_runtime.h>
#include <math.h>

#define BB 2
#define NN 2048
#define DM 512
#define NH 8
#define HD 64
#define TOPK 64
#define BH (BB*NH)       // 16
#define M_TOT (BB*NN)    // 4096
#define SCALEF 0.125f

// ---------------- scratch (static __device__ per allocation rules) ----------
__device__ float g_Qh[BH*NN*HD];            // [bh][n][d]  (Q pre-scaled by 1/8)
__device__ float g_Kh[BH*NN*HD];
__device__ float g_Vh[BH*NN*HD];
__device__ float g_S[(size_t)BH*NN*NN];     // raw scores 256MB
__device__ float g_H[M_TOT*DM];             // merged-head attn output

// ---------------------------------------------------------------------------
// 128x128-tile fp32 GEMM, 8x8 micro-tile, BK=16, 256 threads, double-buffered.
// mode 0: fused QKV (head-split out, Q scaled). mode 1: out-proj from g_H.
// ---------------------------------------------------------------------------
__global__ __launch_bounds__(256)
void gemm128(const float* __restrict__ X0, const float* __restrict__ X1,
             const float* __restrict__ X2,
             const float* __restrict__ W0, const float* __restrict__ W1,
             const float* __restrict__ W2,
             const float* __restrict__ b0, const float* __restrict__ b1,
             const float* __restrict__ b2,
             float* __restrict__ outp, int mode)
{
    __shared__ float XsT[2][16][132];
    __shared__ float WsT[2][16][132];

    const int tid = threadIdx.x;
    const int tx = tid & 15, ty = tid >> 4;
    const int m0 = blockIdx.y * 128;

    int which = 0, o0 = 0;
    const float *X, *W, *bias;
    if (mode == 0) {
        which = blockIdx.x >> 2;
        o0 = (blockIdx.x & 3) * 128;
        X    = (which == 0) ? X0 : (which == 1) ? X1 : X2;
        W    = (which == 0) ? W0 : (which == 1) ? W1 : W2;
        bias = (which == 0) ? b0 : (which == 1) ? b1 : b2;
    } else {
        o0 = blockIdx.x * 128;
        X = g_H; W = W0; bias = b0;
    }

    const int lr  = tid >> 2;
    const int lc4 = (tid & 3) * 4;

    float acc[8][8];
#pragma unroll
    for (int i = 0; i < 8; i++)
#pragma unroll
        for (int j = 0; j < 8; j++) acc[i][j] = 0.f;

    float4 xr[2], wr[2];
#pragma unroll
    for (int j = 0; j < 2; j++) {
        int r = lr + j * 64;
        xr[j] = *(const float4*)&X[(size_t)(m0 + r) * DM + lc4];
        wr[j] = *(const float4*)&W[(size_t)(o0 + r) * DM + lc4];
    }
#pragma unroll
    for (int j = 0; j < 2; j++) {
        int r = lr + j * 64;
        XsT[0][lc4 + 0][r] = xr[j].x; XsT[0][lc4 + 1][r] = xr[j].y;
        XsT[0][lc4 + 2][r] = xr[j].z; XsT[0][lc4 + 3][r] = xr[j].w;
        WsT[0][lc4 + 0][r] = wr[j].x; WsT[0][lc4 + 1][r] = wr[j].y;
        WsT[0][lc4 + 2][r] = wr[j].z; WsT[0][lc4 + 3][r] = wr[j].w;
    }
    __syncthreads();

    int p = 0;
    for (int k0 = 0; k0 < DM; k0 += 16) {
        const int kn = k0 + 16;
        if (kn < DM) {
#pragma unroll
            for (int j = 0; j < 2; j++) {
                int r = lr + j * 64;
                xr[j] = *(const float4*)&X[(size_t)(m0 + r) * DM + kn + lc4];
                wr[j] = *(const float4*)&W[(size_t)(o0 + r) * DM + kn + lc4];
            }
        }
#pragma unroll
        for (int kk = 0; kk < 16; kk++) {
            float4 a0 = *(const float4*)&XsT[p][kk][ty * 4];
            float4 a1 = *(const float4*)&XsT[p][kk][64 + ty * 4];
            float4 bv0 = *(const float4*)&WsT[p][kk][tx * 4];
            float4 bv1 = *(const float4*)&WsT[p][kk][64 + tx * 4];
            float a[8] = {a0.x, a0.y, a0.z, a0.w, a1.x, a1.y, a1.z, a1.w};
            float b[8] = {bv0.x, bv0.y, bv0.z, bv0.w, bv1.x, bv1.y, bv1.z, bv1.w};
#pragma unroll
            for (int i = 0; i < 8; i++)
#pragma unroll
                for (int j = 0; j < 8; j++) acc[i][j] += a[i] * b[j];
        }
        if (kn < DM) {
            int pn = p ^ 1;
#pragma unroll
            for (int j = 0; j < 2; j++) {
                int r = lr + j * 64;
                XsT[pn][lc4 + 0][r] = xr[j].x; XsT[pn][lc4 + 1][r] = xr[j].y;
                XsT[pn][lc4 + 2][r] = xr[j].z; XsT[pn][lc4 + 3][r] = xr[j].w;
                WsT[pn][lc4 + 0][r] = wr[j].x; WsT[pn][lc4 + 1][r] = wr[j].y;
                WsT[pn][lc4 + 2][r] = wr[j].z; WsT[pn][lc4 + 3][r] = wr[j].w;
            }
        }
        __syncthreads();
        p ^= 1;
    }

    const float sc = (mode == 0 && which == 0) ? SCALEF : 1.f;
#pragma unroll
    for (int i = 0; i < 8; i++) {
        int m = m0 + ((i < 4) ? ty * 4 + i : 64 + ty * 4 + (i - 4));
#pragma unroll
        for (int jg = 0; jg < 2; jg++) {
            int oc = o0 + ((jg == 0) ? tx * 4 : 64 + tx * 4);
            float4 v;
            v.x = (acc[i][jg * 4 + 0] + bias[oc + 0]) * sc;
            v.y = (acc[i][jg * 4 + 1] + bias[oc + 1]) * sc;
            v.z = (acc[i][jg * 4 + 2] + bias[oc + 2]) * sc;
            v.w = (acc[i][jg * 4 + 3] + bias[oc + 3]) * sc;
            if (mode == 0) {
                int b = m >> 11, n = m & (NN - 1);
                int h = oc >> 6, d = oc & 63;
                float* dst = (which == 0) ? g_Qh : (which == 1) ? g_Kh : g_Vh;
                *(float4*)&dst[(size_t)((b * NH + h) * NN + n) * HD + d] = v;
            } else {
                *(float4*)&outp[(size_t)m * DM + oc] = v;
            }
        }
    }
}

// ---------------------------------------------------------------------------
// Scores (round-2 proven version): per (b,h), S = Qh @ Kh^T (Q pre-scaled).
// 128x128 tiles, 8x8 micro-tile, 2 x BK=32 stages. grid (16,16,16).
// ---------------------------------------------------------------------------
__global__ __launch_bounds__(256)
void scores_kernel()
{
    __shared__ float QsT[32][132];
    __shared__ float KsT[32][132];

    const int bh = blockIdx.z;
    const int kx = blockIdx.x * 128;
    const int qy = blockIdx.y * 128;
    const int tid = threadIdx.x;
    const int tx = tid & 15, ty = tid >> 4;

    float acc[8][8];
#pragma unroll
    for (int i = 0; i < 8; i++)
#pragma unroll
        for (int j = 0; j < 8; j++) acc[i][j] = 0.f;

    for (int kb = 0; kb < HD; kb += 32) {
#pragma unroll
        for (int j = 0; j < 4; j++) {
            int i = tid + j * 256;
            int r = i >> 3, c4 = (i & 7) * 4;
            float4 qv = *(const float4*)&g_Qh[((size_t)bh * NN + qy + r) * HD + kb + c4];
            QsT[c4 + 0][r] = qv.x; QsT[c4 + 1][r] = qv.y;
            QsT[c4 + 2][r] = qv.z; QsT[c4 + 3][r] = qv.w;
            float4 kv = *(const float4*)&g_Kh[((size_t)bh * NN + kx + r) * HD + kb + c4];
            KsT[c4 + 0][r] = kv.x; KsT[c4 + 1][r] = kv.y;
            KsT[c4 + 2][r] = kv.z; KsT[c4 + 3][r] = kv.w;
        }
        __syncthreads();
#pragma unroll
        for (int kk = 0; kk < 32; kk++) {
            float4 a0 = *(const float4*)&QsT[kk][ty * 4];
            float4 a1 = *(const float4*)&QsT[kk][64 + ty * 4];
            float4 bv0 = *(const float4*)&KsT[kk][tx * 4];
            float4 bv1 = *(const float4*)&KsT[kk][64 + tx * 4];
            float a[8] = {a0.x, a0.y, a0.z, a0.w, a1.x, a1.y, a1.z, a1.w};
            float b[8] = {bv0.x, bv0.y, bv0.z, bv0.w, bv1.x, bv1.y, bv1.z, bv1.w};
#pragma unroll
            for (int i = 0; i < 8; i++)
#pragma unroll
                for (int j = 0; j < 8; j++) acc[i][j] += a[i] * b[j];
        }
        __syncthreads();
    }

#pragma unroll
    for (int i = 0; i < 8; i++) {
        int row = qy + ((i < 4) ? ty * 4 + i : 64 + ty * 4 + (i - 4));
#pragma unroll
        for (int jg = 0; jg < 2; jg++) {
            int col = kx + ((jg == 0) ? tx * 4 : 64 + tx * 4);
            float4 v = make_float4(acc[i][jg * 4 + 0], acc[i][jg * 4 + 1],
                                   acc[i][jg * 4 + 2], acc[i][jg * 4 + 3]);
            __stcs((float4*)&g_S[((size_t)bh * NN + row) * NN + col], v);
        }
    }
}

// ---------------------------------------------------------------------------
// WARP-PER-ROW topk + softmax + AV. 8 warps/block, one row per warp.
// 64 keys/lane in regs; warp-private 256-bin smem hist; all cross-lane
// coordination via shuffles/ballot; NO __syncthreads. grid 4096 x 256.
// Exact 4x8-bit MSB radix select (same semantics as round-2 version).
// ---------------------------------------------------------------------------
__device__ __forceinline__ float key2float(unsigned k) {
    unsigned u = (k & 0x80000000u) ? (k & 0x7fffffffu) : ~k;
    return __uint_as_float(u);
}

__global__ __launch_bounds__(256)
void topk_av_warp(float* __restrict__ attn, int write_attn)
{
    const int wid  = threadIdx.x >> 5;        // 0..7
    const int lane = threadIdx.x & 31;
    const int row  = blockIdx.x * 8 + wid;    // bh*N + q
    const int bh   = row >> 11;
    const int q    = row & (NN - 1);

    __shared__ int   hist_s[8][256];
    __shared__ int   sidx_s[8][96];
    __shared__ float sw_s[8][96];
    __shared__ int   cnt_s[8];

    int*   hist = hist_s[wid];
    int*   sidx = sidx_s[wid];
    float* sw   = sw_s[wid];

    // ---- load 64 scores/lane as monotone uint keys (coalesced float4) ----
    const float4* Srow = (const float4*)&g_S[(size_t)row * NN];
    unsigned keys[64];
#pragma unroll
    for (int i = 0; i < 16; i++) {
        float4 v = __ldcs(&Srow[i * 32 + lane]);
        float f[4] = {v.x, v.y, v.z, v.w};
#pragma unroll
        for (int j = 0; j < 4; j++) {
            unsigned u = __float_as_uint(f[j]);
            keys[i * 4 + j] = (u & 0x80000000u) ? ~u : (u | 0x80000000u);
        }
    }
    if (lane == 0) cnt_s[wid] = 0;

    // ---- exact 64th-largest via 4 x 8-bit MSB radix passes ----
    unsigned prefix = 0;
    int kk = TOPK;
    for (int pass = 0; pass < 4; pass++) {
        const int shift = 24 - 8 * pass;
#pragma unroll
        for (int j = 0; j < 8; j++) hist[lane * 8 + j] = 0;
        __syncwarp();

        if (pass == 0) {
            // dense pass: warp-aggregate atomics (exponent bins cluster hard)
#pragma unroll
            for (int e = 0; e < 64; e++) {
                unsigned bin = keys[e] >> 24;
                unsigned mm = __match_any_sync(0xffffffffu, bin);
                if ((int)(__ffs(mm) - 1) == lane)
                    atomicAdd(&hist[bin], __popc(mm));
            }
        } else {
#pragma unroll
            for (int e = 0; e < 64; e++) {
                unsigned k = keys[e];
                unsigned hi = (k >> (31 - 8 * pass)) >> 1;   // top 8*pass bits
                if (hi == prefix) atomicAdd(&hist[(k >> shift) & 255u], 1);
            }
        }
        __syncwarp();

        // suffix-scan 256 bins: 8 bins/lane + warp shuffle suffix scan
        int h[8], ls[8];
#pragma unroll
        for (int j = 0; j < 8; j++) h[j] = hist[lane * 8 + j];
        int tot = 0;
#pragma unroll
        for (int j = 7; j >= 0; j--) { tot += h[j]; ls[j] = tot; }
        int s = tot;
#pragma unroll
        for (int off = 1; off < 32; off <<= 1) {
            int t = __shfl_down_sync(0xffffffffu, s, off);
            if (lane + off < 32) s += t;
        }
        const int G = s - tot;              // count in bins of strictly higher lanes
        int foundBin = -1, newkk = 0;
#pragma unroll
        for (int j = 0; j < 8; j++) {
            int ge = ls[j] + G;
            int gt = ge - h[j];
            if (ge >= kk && gt < kk && h[j] > 0) {
                foundBin = lane * 8 + j;
                newkk = kk - gt;
            }
        }
        unsigned bal = __ballot_sync(0xffffffffu, foundBin >= 0);
        int src = __ffs(bal) - 1;
        foundBin = __shfl_sync(0xffffffffu, foundBin, src);
        newkk    = __shfl_sync(0xffffffffu, newkk, src);
        prefix = (prefix << 8) | (unsigned)foundBin;
        kk = newkk;
        __syncwarp();
    }
    const unsigned kth = prefix;            // exact 64th-largest key

    // ---- row max (key order == float order) ----
    unsigned kmax = 0;
#pragma unroll
    for (int e = 0; e < 64; e++) kmax = (keys[e] > kmax) ? keys[e] : kmax;
#pragma unroll
    for (int off = 16; off > 0; off >>= 1) {
        unsigned t = __shfl_xor_sync(0xffffffffu, kmax, off);
        kmax = (t > kmax) ? t : kmax;
    }
    const float rmax = key2float(kmax);

    // ---- sum of exp over selected ----
    float lsum = 0.f;
#pragma unroll
    for (int e = 0; e < 64; e++)
        if (keys[e] >= kth) lsum += __expf(key2float(keys[e]) - rmax);
#pragma unroll
    for (int off = 16; off > 0; off >>= 1)
        lsum += __shfl_xor_sync(0xffffffffu, lsum, off);
    const float inv_z = 1.f / lsum;

    // ---- write attn row + gather selected (idx, w) into warp smem ----
    float4* Arow = (float4*)&attn[(size_t)row * NN];
#pragma unroll
    for (int i = 0; i < 16; i++) {
        float wv[4];
#pragma unroll
        for (int j = 0; j < 4; j++) {
            unsigned k = keys[i * 4 + j];
            bool sel = (k >= kth);
            float w = sel ? __expf(key2float(k) - rmax) * inv_z : 0.f;
            wv[j] = w;
            if (sel) {
                int p = atomicAdd(&cnt_s[wid], 1);
                if (p < 96) { sidx[p] = (i * 32 + lane) * 4 + j; sw[p] = w; }
            }
        }
        if (write_attn)
            __stcs(&Arow[i * 32 + lane], make_float4(wv[0], wv[1], wv[2], wv[3]));
    }
    __syncwarp();
    int cnt = cnt_s[wid]; if (cnt > 96) cnt = 96;

    // ---- AV: 64 dims across 32 lanes (float2/lane), ~64 selected terms ----
    const float2* Vbase = (const float2*)&g_Vh[(size_t)bh * NN * HD];
    float a0 = 0.f, a1 = 0.f;
    for (int j = 0; j < cnt; j++) {
        float wj = sw[j];
        float2 vv = Vbase[(size_t)sidx[j] * 32 + lane];
        a0 += wj * vv.x;
        a1 += wj * vv.y;
    }
    int b = bh >> 3, h = bh & 7;
    float2* Hp = (float2*)&g_H[(size_t)(b * NN + q) * DM + h * HD];
    Hp[lane] = make_float2(a0, a1);
}

// ---------------------------------------------------------------------------
extern "C" void kernel_launch(void* const* d_in, const int* in_sizes, int n_in,
                              void* d_out, int out_size)
{
    const float* q  = (const float*)d_in[0];
    const float* k  = (const float*)d_in[1];
    const float* v  = (const float*)d_in[2];
    const float* wq = (const float*)d_in[3];
    const float* bq = (const float*)d_in[4];
    const float* wk = (const float*)d_in[5];
    const float* bk = (const float*)d_in[6];
    const float* wv = (const float*)d_in[7];
    const float* bv = (const float*)d_in[8];
    const float* wo = (const float*)d_in[9];
    const float* bo = (const float*)d_in[10];

    float* out = (float*)d_out;
    const long long OUT_ELEMS  = (long long)M_TOT * DM;        // 2,097,152
    const long long ATTN_ELEMS = (long long)BH * NN * NN;      // 67,108,864

    int write_attn = 0, write_out = 1;
    float* attn_ptr = nullptr;
    if ((long long)out_size >= OUT_ELEMS + ATTN_ELEMS) {
        write_attn = 1; attn_ptr = out + OUT_ELEMS;
    } else if ((long long)out_size == ATTN_ELEMS) {
        write_attn = 1; attn_ptr = out; write_out = 0;
    }

    gemm128<<<dim3(12, M_TOT / 128), 256>>>(q, k, v, wq, wk, wv, bq, bk, bv,
                                            nullptr, 0);

    scores_kernel<<<dim3(NN / 128, NN / 128, BH), 256>>>();

    topk_av_warp<<<BH * NN / 8, 256>>>(attn_ptr, write_attn);

    if (write_out)
        gemm128<<<dim3(DM / 128, M_TOT / 128), 256>>>(nullptr, nullptr, nullptr,
                                                      wo, nullptr, nullptr,
                                                      bo, nullptr, nullptr,
                                                      out, 1);
}